// round 6
// baseline (speedup 1.0000x reference)
#include <cuda_runtime.h>
#include <math.h>

#define BSZ 2
#define SEQ 2048
#define EMB 1024
#define NH  16
#define HD  64
#define MROWS (BSZ * SEQ)          /* 4096 */
#define NQG   (NH * HD + NH)       /* 1040 = Wq/bq column count (Q 0..1023, gates 1024..1039) */

// Scratch (static device globals — no allocation allowed anywhere)
__device__ float g_Q   [MROWS * EMB];  // Q projection
__device__ float g_Gate[MROWS * NH];   // sigmoid(gate_logits)
__device__ float g_K   [MROWS * EMB];
__device__ float g_V   [MROWS * EMB];
__device__ float g_AO  [MROWS * EMB];  // gated attention output, pre-Wo

// ---------------------------------------------------------------------------
// Tiled SGEMM with bias: C[M,N] = A[M,K] @ B[K,N(ldb)] + bias[N]
// BM=BN=64, BK=16, 256 threads, 4x4 register tile per thread.
// ldb/ldc allow B with wider row stride (Wq has 1040 cols; we compute 1024).
// DST selects scratch-global source/dest so kernel_launch stays launch-only:
//   DST=0: C=g_Q    DST=1: C=g_K    DST=2: C=g_V    DST=3: A=g_AO, C=param
// ---------------------------------------------------------------------------
template<int DST>
__global__ __launch_bounds__(256)
void sgemm_bias(const float* __restrict__ Ap, const float* __restrict__ B,
                const float* __restrict__ bias, float* __restrict__ Cp,
                int M, int N, int K, int ldb, int ldc)
{
    const float* A = (DST == 3) ? (const float*)g_AO : Ap;
    float* C = (DST == 0) ? (float*)g_Q
             : (DST == 1) ? (float*)g_K
             : (DST == 2) ? (float*)g_V
             : Cp;

    __shared__ float As[16][68];   // [k][m] (transposed store)
    __shared__ float Bs[16][64];   // [k][n]

    const int tid = threadIdx.x;
    const int tx = tid & 15;       // -> N
    const int ty = tid >> 4;       // -> M
    const int row0 = blockIdx.y * 64;
    const int col0 = blockIdx.x * 64;

    const int arow = tid >> 2;            // 0..63
    const int acol = (tid & 3) << 2;      // 0,4,8,12
    const int brow = tid >> 4;            // 0..15
    const int bcol = (tid & 15) << 2;     // 0..60

    float acc[4][4] = {};

    for (int kb = 0; kb < K; kb += 16) {
        float4 a = *(const float4*)&A[(size_t)(row0 + arow) * K + kb + acol];
        float4 bb = *(const float4*)&B[(size_t)(kb + brow) * ldb + col0 + bcol];
        As[acol + 0][arow] = a.x;
        As[acol + 1][arow] = a.y;
        As[acol + 2][arow] = a.z;
        As[acol + 3][arow] = a.w;
        *(float4*)&Bs[brow][bcol] = bb;
        __syncthreads();

#pragma unroll
        for (int k = 0; k < 16; ++k) {
            float ra[4], rb[4];
#pragma unroll
            for (int i = 0; i < 4; ++i) ra[i] = As[k][ty * 4 + i];
#pragma unroll
            for (int j = 0; j < 4; ++j) rb[j] = Bs[k][tx * 4 + j];
#pragma unroll
            for (int i = 0; i < 4; ++i)
#pragma unroll
                for (int j = 0; j < 4; ++j)
                    acc[i][j] = fmaf(ra[i], rb[j], acc[i][j]);
        }
        __syncthreads();
    }

#pragma unroll
    for (int i = 0; i < 4; ++i) {
        const int row = row0 + ty * 4 + i;
        const int col = col0 + tx * 4;
        float4 o;
        o.x = acc[i][0] + bias[col + 0];
        o.y = acc[i][1] + bias[col + 1];
        o.z = acc[i][2] + bias[col + 2];
        o.w = acc[i][3] + bias[col + 3];
        *(float4*)&C[(size_t)row * ldc + col] = o;
    }
}

// ---------------------------------------------------------------------------
// Gate kernel: g_Gate[row][h] = sigmoid(X[row] . Wq[:, 1024+h] + bq[1024+h]).
// One warp per row, 16 heads per warp (float4 loads of the 16 gate columns).
// grid = MROWS/4, block = 128 (4 warps).
// ---------------------------------------------------------------------------
__global__ __launch_bounds__(128)
void gate_proj(const float* __restrict__ X, const float* __restrict__ Wq,
               const float* __restrict__ bq)
{
    const int warp = threadIdx.x >> 5;
    const int lane = threadIdx.x & 31;
    const int row  = blockIdx.x * 4 + warp;

    float acc[16] = {};
    for (int e = lane; e < EMB; e += 32) {
        const float xv = X[(size_t)row * EMB + e];
        const float* wrow = &Wq[(size_t)e * NQG + NH * HD];
        const float4 w0 = *(const float4*)&wrow[0];
        const float4 w1 = *(const float4*)&wrow[4];
        const float4 w2 = *(const float4*)&wrow[8];
        const float4 w3 = *(const float4*)&wrow[12];
        acc[0]  = fmaf(xv, w0.x, acc[0]);  acc[1]  = fmaf(xv, w0.y, acc[1]);
        acc[2]  = fmaf(xv, w0.z, acc[2]);  acc[3]  = fmaf(xv, w0.w, acc[3]);
        acc[4]  = fmaf(xv, w1.x, acc[4]);  acc[5]  = fmaf(xv, w1.y, acc[5]);
        acc[6]  = fmaf(xv, w1.z, acc[6]);  acc[7]  = fmaf(xv, w1.w, acc[7]);
        acc[8]  = fmaf(xv, w2.x, acc[8]);  acc[9]  = fmaf(xv, w2.y, acc[9]);
        acc[10] = fmaf(xv, w2.z, acc[10]); acc[11] = fmaf(xv, w2.w, acc[11]);
        acc[12] = fmaf(xv, w3.x, acc[12]); acc[13] = fmaf(xv, w3.y, acc[13]);
        acc[14] = fmaf(xv, w3.z, acc[14]); acc[15] = fmaf(xv, w3.w, acc[15]);
    }
#pragma unroll
    for (int h = 0; h < 16; ++h) {
#pragma unroll
        for (int off = 16; off >= 1; off >>= 1)
            acc[h] += __shfl_xor_sync(0xffffffffu, acc[h], off);
    }
    if (lane < 16) {
        const float logit = acc[lane] + bq[NH * HD + lane];
        g_Gate[(size_t)row * NH + lane] = 1.f / (1.f + __expf(-logit));
    }
}

// ---------------------------------------------------------------------------
// Flash attention + sigmoid gate. STATIC shared memory (44 KB < 48 KB).
// grid = (S/64 = 32, B*H = 32), block = 128 threads.
// Per block: 64 query rows of one (b,h); loop over 64 kv tiles of 32 cols.
// Thread map: tx = tid&7 (4 S-cols each), ty = tid>>3 (4 S-rows each).
// PV: tx covers 8 output d-cols.
// ---------------------------------------------------------------------------
#define QS_STRIDE 68
#define KS_STRIDE 36
#define PS_STRIDE 68
#define VS_STRIDE 68

__global__ __launch_bounds__(128)
void flash_gated(const float* __restrict__ mask)
{
    __shared__ float Qs[64 * QS_STRIDE];  // [d][r], scale pre-applied
    __shared__ float Ks[64 * KS_STRIDE];  // [d][c]
    __shared__ float Ps[32 * PS_STRIDE];  // [t][r]
    __shared__ float Vs[32 * VS_STRIDE];  // [t][d]

    const int bh = blockIdx.y;
    const int b  = bh >> 4;
    const int h  = bh & 15;
    const int s0 = blockIdx.x * 64;

    const int tid = threadIdx.x;
    const int tx = tid & 7;    // score cols (4 each)
    const int ty = tid >> 3;   // score rows (4 each)
    const int r4 = ty * 4;
    const int c4 = tx * 4;
    const int d8 = tx * 8;     // output d-cols (8 each)

    const float scale = 0.125f;  // 1/sqrt(64)

    // ---- load Q tile (scaled) into Qs[d][r] ----
#pragma unroll
    for (int it = 0; it < 8; ++it) {
        int idx = tid + it * 128;          // 0..1023
        int r  = idx >> 4;                 // 0..63
        int dg = (idx & 15) << 2;          // 0..60
        float4 q = *(const float4*)&g_Q[(size_t)(b * SEQ + s0 + r) * EMB + h * HD + dg];
        Qs[(dg + 0) * QS_STRIDE + r] = q.x * scale;
        Qs[(dg + 1) * QS_STRIDE + r] = q.y * scale;
        Qs[(dg + 2) * QS_STRIDE + r] = q.z * scale;
        Qs[(dg + 3) * QS_STRIDE + r] = q.w * scale;
    }

    float o[4][8] = {};
    float m[4], l[4];
#pragma unroll
    for (int i = 0; i < 4; ++i) { m[i] = -INFINITY; l[i] = 0.f; }

    for (int jt = 0; jt < SEQ / 32; ++jt) {
        const int t0 = jt * 32;
        __syncthreads();   // prev iter's Ps/Vs reads done; Qs ready first time

        // ---- load K tile into Ks[d][c] and V tile into Vs[t][d] ----
#pragma unroll
        for (int it = 0; it < 4; ++it) {
            int idx = tid + it * 128;       // 0..511
            int c  = idx >> 4;              // 0..31
            int dg = (idx & 15) << 2;       // 0..60
            float4 k = *(const float4*)&g_K[(size_t)(b * SEQ + t0 + c) * EMB + h * HD + dg];
            Ks[(dg + 0) * KS_STRIDE + c] = k.x;
            Ks[(dg + 1) * KS_STRIDE + c] = k.y;
            Ks[(dg + 2) * KS_STRIDE + c] = k.z;
            Ks[(dg + 3) * KS_STRIDE + c] = k.w;
            float4 v = *(const float4*)&g_V[(size_t)(b * SEQ + t0 + c) * EMB + h * HD + dg];
            *(float4*)&Vs[c * VS_STRIDE + dg] = v;
        }
        __syncthreads();

        // ---- scores S = Q^T K (contraction over d), vectorized LDS.128 ----
        float acc[4][4] = {};
#pragma unroll 8
        for (int d = 0; d < 64; ++d) {
            const float4 ra = *(const float4*)&Qs[d * QS_STRIDE + r4];
            const float4 rb = *(const float4*)&Ks[d * KS_STRIDE + c4];
            const float a0 = ra.x, a1 = ra.y, a2 = ra.z, a3 = ra.w;
            acc[0][0] = fmaf(a0, rb.x, acc[0][0]); acc[0][1] = fmaf(a0, rb.y, acc[0][1]);
            acc[0][2] = fmaf(a0, rb.z, acc[0][2]); acc[0][3] = fmaf(a0, rb.w, acc[0][3]);
            acc[1][0] = fmaf(a1, rb.x, acc[1][0]); acc[1][1] = fmaf(a1, rb.y, acc[1][1]);
            acc[1][2] = fmaf(a1, rb.z, acc[1][2]); acc[1][3] = fmaf(a1, rb.w, acc[1][3]);
            acc[2][0] = fmaf(a2, rb.x, acc[2][0]); acc[2][1] = fmaf(a2, rb.y, acc[2][1]);
            acc[2][2] = fmaf(a2, rb.z, acc[2][2]); acc[2][3] = fmaf(a2, rb.w, acc[2][3]);
            acc[3][0] = fmaf(a3, rb.x, acc[3][0]); acc[3][1] = fmaf(a3, rb.y, acc[3][1]);
            acc[3][2] = fmaf(a3, rb.z, acc[3][2]); acc[3][3] = fmaf(a3, rb.w, acc[3][3]);
        }

        // ---- add mask ----
#pragma unroll
        for (int i = 0; i < 4; ++i) {
            const float4 mk = *(const float4*)&mask[(size_t)(b * SEQ + s0 + r4 + i) * SEQ + t0 + c4];
            acc[i][0] += mk.x; acc[i][1] += mk.y; acc[i][2] += mk.z; acc[i][3] += mk.w;
        }

        // ---- online softmax: each row is shared by 8 lanes (same ty) ----
        float fac[4];
#pragma unroll
        for (int i = 0; i < 4; ++i) {
            float lm = fmaxf(fmaxf(acc[i][0], acc[i][1]), fmaxf(acc[i][2], acc[i][3]));
#pragma unroll
            for (int off = 4; off >= 1; off >>= 1)
                lm = fmaxf(lm, __shfl_xor_sync(0xffffffffu, lm, off, 8));
            const float mn = fmaxf(m[i], lm);
            fac[i] = __expf(m[i] - mn);
            float rs = 0.f;
#pragma unroll
            for (int j = 0; j < 4; ++j) {
                acc[i][j] = __expf(acc[i][j] - mn);
                rs += acc[i][j];
            }
#pragma unroll
            for (int off = 4; off >= 1; off >>= 1)
                rs += __shfl_xor_sync(0xffffffffu, rs, off, 8);
            l[i] = l[i] * fac[i] + rs;
            m[i] = mn;
        }

        // ---- write P (transposed: [t][r]) ----
#pragma unroll
        for (int j = 0; j < 4; ++j)
#pragma unroll
            for (int i = 0; i < 4; ++i)
                Ps[(c4 + j) * PS_STRIDE + (r4 + i)] = acc[i][j];

        __syncthreads();  // Ps visible to all

        // ---- O = O*fac + P @ V ----
#pragma unroll
        for (int i = 0; i < 4; ++i)
#pragma unroll
            for (int j = 0; j < 8; ++j)
                o[i][j] *= fac[i];

#pragma unroll 4
        for (int t = 0; t < 32; ++t) {
            const float4 rp = *(const float4*)&Ps[t * PS_STRIDE + r4];
            const float4 va = *(const float4*)&Vs[t * VS_STRIDE + d8];
            const float4 vb = *(const float4*)&Vs[t * VS_STRIDE + d8 + 4];
            const float p0 = rp.x, p1 = rp.y, p2 = rp.z, p3 = rp.w;
            o[0][0] = fmaf(p0, va.x, o[0][0]); o[0][1] = fmaf(p0, va.y, o[0][1]);
            o[0][2] = fmaf(p0, va.z, o[0][2]); o[0][3] = fmaf(p0, va.w, o[0][3]);
            o[0][4] = fmaf(p0, vb.x, o[0][4]); o[0][5] = fmaf(p0, vb.y, o[0][5]);
            o[0][6] = fmaf(p0, vb.z, o[0][6]); o[0][7] = fmaf(p0, vb.w, o[0][7]);
            o[1][0] = fmaf(p1, va.x, o[1][0]); o[1][1] = fmaf(p1, va.y, o[1][1]);
            o[1][2] = fmaf(p1, va.z, o[1][2]); o[1][3] = fmaf(p1, va.w, o[1][3]);
            o[1][4] = fmaf(p1, vb.x, o[1][4]); o[1][5] = fmaf(p1, vb.y, o[1][5]);
            o[1][6] = fmaf(p1, vb.z, o[1][6]); o[1][7] = fmaf(p1, vb.w, o[1][7]);
            o[2][0] = fmaf(p2, va.x, o[2][0]); o[2][1] = fmaf(p2, va.y, o[2][1]);
            o[2][2] = fmaf(p2, va.z, o[2][2]); o[2][3] = fmaf(p2, va.w, o[2][3]);
            o[2][4] = fmaf(p2, vb.x, o[2][4]); o[2][5] = fmaf(p2, vb.y, o[2][5]);
            o[2][6] = fmaf(p2, vb.z, o[2][6]); o[2][7] = fmaf(p2, vb.w, o[2][7]);
            o[3][0] = fmaf(p3, va.x, o[3][0]); o[3][1] = fmaf(p3, va.y, o[3][1]);
            o[3][2] = fmaf(p3, va.z, o[3][2]); o[3][3] = fmaf(p3, va.w, o[3][3]);
            o[3][4] = fmaf(p3, vb.x, o[3][4]); o[3][5] = fmaf(p3, vb.y, o[3][5]);
            o[3][6] = fmaf(p3, vb.z, o[3][6]); o[3][7] = fmaf(p3, vb.w, o[3][7]);
        }
    }

    // ---- epilogue: 1/l, sigmoid gate, store (8 d-cols per thread) ----
#pragma unroll
    for (int i = 0; i < 4; ++i) {
        const int srow = b * SEQ + s0 + r4 + i;
        const float gate = g_Gate[(size_t)srow * NH + h];
        const float inv_l = gate / l[i];
        float4 oa, ob;
        oa.x = o[i][0] * inv_l; oa.y = o[i][1] * inv_l;
        oa.z = o[i][2] * inv_l; oa.w = o[i][3] * inv_l;
        ob.x = o[i][4] * inv_l; ob.y = o[i][5] * inv_l;
        ob.z = o[i][6] * inv_l; ob.w = o[i][7] * inv_l;
        *(float4*)&g_AO[(size_t)srow * EMB + h * HD + d8]     = oa;
        *(float4*)&g_AO[(size_t)srow * EMB + h * HD + d8 + 4] = ob;
    }
}

// ---------------------------------------------------------------------------
// kernel_launch: KERNEL LAUNCHES ONLY (graph-capture safe).
// ---------------------------------------------------------------------------
extern "C" void kernel_launch(void* const* d_in, const int* in_sizes, int n_in,
                              void* d_out, int out_size)
{
    const float* X    = (const float*)d_in[0];
    const float* mask = (const float*)d_in[1];
    const float* Wq   = (const float*)d_in[2];
    const float* bq   = (const float*)d_in[3];
    const float* Wk   = (const float*)d_in[4];
    const float* bk   = (const float*)d_in[5];
    const float* Wv   = (const float*)d_in[6];
    const float* bv   = (const float*)d_in[7];
    const float* Wo   = (const float*)d_in[8];
    const float* bo   = (const float*)d_in[9];
    float* out = (float*)d_out;

    dim3 blk(256);

    // Q = X @ Wq[:, :1024] + bq[:1024]   (Wq row stride is NQG=1040)
    sgemm_bias<0><<<dim3(EMB / 64, MROWS / 64), blk>>>(X, Wq, bq, nullptr, MROWS, EMB, EMB, NQG, EMB);
    // Gate = sigmoid(X @ Wq[:, 1024:1040] + bq[1024:1040])
    gate_proj<<<MROWS / 4, 128>>>(X, Wq, bq);
    // K = X @ Wk + bk
    sgemm_bias<1><<<dim3(EMB / 64, MROWS / 64), blk>>>(X, Wk, bk, nullptr, MROWS, EMB, EMB, EMB, EMB);
    // V = X @ Wv + bv
    sgemm_bias<2><<<dim3(EMB / 64, MROWS / 64), blk>>>(X, Wv, bv, nullptr, MROWS, EMB, EMB, EMB, EMB);

    // flash attention with gate -> g_AO
    flash_gated<<<dim3(SEQ / 64, BSZ * NH), dim3(128)>>>(mask);

    // out = g_AO @ Wo + bo
    sgemm_bias<3><<<dim3(EMB / 64, MROWS / 64), blk>>>(nullptr, Wo, bo, out, MROWS, EMB, EMB, EMB, EMB);
}

// round 7
// speedup vs baseline: 1.1466x; 1.1466x over previous
#include <cuda_runtime.h>
#include <math.h>

#define BSZ 2
#define SEQ 2048
#define EMB 1024
#define NH  16
#define HD  64
#define MROWS (BSZ * SEQ)          /* 4096 */
#define NQG   (NH * HD + NH)       /* 1040: Wq/bq cols (Q 0..1023, gates 1024..1039) */

// Scratch (static device globals — no allocation allowed anywhere)
__device__ float g_Q   [MROWS * EMB];
__device__ float g_Gate[MROWS * NH];
__device__ float g_K   [MROWS * EMB];
__device__ float g_V   [MROWS * EMB];
__device__ float g_AO  [MROWS * EMB];

// ---------------------------------------------------------------------------
// SGEMM 128x128x16, 256 threads, 8x8 split micro-tile (rows r, r+64 / cols
// c, c+64), register-prefetch double buffering. M=4096, N=1024, K=1024 fixed.
// MODE 0: fused QKV — blockIdx.z selects {Wq->g_Q (ldb NQG), Wk->g_K, Wv->g_V}
// MODE 1: out = g_AO @ Wo + bo
// ---------------------------------------------------------------------------
template<int MODE>
__global__ __launch_bounds__(256, 2)
void sgemm128(const float* __restrict__ X,
              const float* __restrict__ W0, const float* __restrict__ b0,
              const float* __restrict__ W1, const float* __restrict__ b1,
              const float* __restrict__ W2, const float* __restrict__ b2,
              float* __restrict__ outp)
{
    const float* A; const float* B; const float* bias; float* C; int ldb;
    if (MODE == 0) {
        A = X;
        const int z = blockIdx.z;
        if (z == 0)      { B = W0; bias = b0; C = g_Q; ldb = NQG; }
        else if (z == 1) { B = W1; bias = b1; C = g_K; ldb = EMB; }
        else             { B = W2; bias = b2; C = g_V; ldb = EMB; }
    } else {
        A = g_AO; B = W0; bias = b0; C = outp; ldb = EMB;
    }

    __shared__ float As[16][132];   // A^T tile: [k][m]
    __shared__ float Bs[16][132];   // B tile:   [k][n]

    const int tid = threadIdx.x;
    const int tx = tid & 15;        // -> 4+4 cols (c, c+64)
    const int ty = tid >> 4;        // -> 4+4 rows (r, r+64)
    const int row0 = blockIdx.y * 128;
    const int col0 = blockIdx.x * 128;

    // global load mapping
    const int arow = tid >> 2;            // 0..63  (+64 on second it)
    const int akc  = (tid & 3) << 2;      // 0,4,8,12
    const int brow = tid >> 5;            // 0..7   (+8 on second it)
    const int bcol = (tid & 31) << 2;     // 0..124

    float4 pa0, pa1, pb0, pb1;

    // prologue: prefetch kb=0 tile
    pa0 = *(const float4*)&A[(size_t)(row0 + arow) * EMB + akc];
    pa1 = *(const float4*)&A[(size_t)(row0 + arow + 64) * EMB + akc];
    pb0 = *(const float4*)&B[(size_t)(brow) * ldb + col0 + bcol];
    pb1 = *(const float4*)&B[(size_t)(brow + 8) * ldb + col0 + bcol];

    float acc[8][8] = {};

    for (int kb = 0; kb < EMB; kb += 16) {
        __syncthreads();   // previous compute done reading smem
        As[akc + 0][arow] = pa0.x;  As[akc + 1][arow] = pa0.y;
        As[akc + 2][arow] = pa0.z;  As[akc + 3][arow] = pa0.w;
        As[akc + 0][arow + 64] = pa1.x;  As[akc + 1][arow + 64] = pa1.y;
        As[akc + 2][arow + 64] = pa1.z;  As[akc + 3][arow + 64] = pa1.w;
        *(float4*)&Bs[brow][bcol]     = pb0;
        *(float4*)&Bs[brow + 8][bcol] = pb1;
        __syncthreads();

        if (kb + 16 < EMB) {
            pa0 = *(const float4*)&A[(size_t)(row0 + arow) * EMB + kb + 16 + akc];
            pa1 = *(const float4*)&A[(size_t)(row0 + arow + 64) * EMB + kb + 16 + akc];
            pb0 = *(const float4*)&B[(size_t)(kb + 16 + brow) * ldb + col0 + bcol];
            pb1 = *(const float4*)&B[(size_t)(kb + 16 + brow + 8) * ldb + col0 + bcol];
        }

#pragma unroll
        for (int k = 0; k < 16; ++k) {
            float ra[8], rb[8];
            const float4 a0 = *(const float4*)&As[k][ty * 4];
            const float4 a1 = *(const float4*)&As[k][64 + ty * 4];
            const float4 b0v = *(const float4*)&Bs[k][tx * 4];
            const float4 b1v = *(const float4*)&Bs[k][64 + tx * 4];
            ra[0] = a0.x; ra[1] = a0.y; ra[2] = a0.z; ra[3] = a0.w;
            ra[4] = a1.x; ra[5] = a1.y; ra[6] = a1.z; ra[7] = a1.w;
            rb[0] = b0v.x; rb[1] = b0v.y; rb[2] = b0v.z; rb[3] = b0v.w;
            rb[4] = b1v.x; rb[5] = b1v.y; rb[6] = b1v.z; rb[7] = b1v.w;
#pragma unroll
            for (int i = 0; i < 8; ++i)
#pragma unroll
                for (int j = 0; j < 8; ++j)
                    acc[i][j] = fmaf(ra[i], rb[j], acc[i][j]);
        }
    }

    // epilogue: bias + store (rows ty*4+i (+64), cols tx*4+j (+64))
#pragma unroll
    for (int ih = 0; ih < 2; ++ih) {
#pragma unroll
        for (int i = 0; i < 4; ++i) {
            const int row = row0 + ih * 64 + ty * 4 + i;
#pragma unroll
            for (int jh = 0; jh < 2; ++jh) {
                const int col = col0 + jh * 64 + tx * 4;
                float4 o;
                o.x = acc[ih * 4 + i][jh * 4 + 0] + bias[col + 0];
                o.y = acc[ih * 4 + i][jh * 4 + 1] + bias[col + 1];
                o.z = acc[ih * 4 + i][jh * 4 + 2] + bias[col + 2];
                o.w = acc[ih * 4 + i][jh * 4 + 3] + bias[col + 3];
                *(float4*)&C[(size_t)row * EMB + col] = o;
            }
        }
    }
}

// ---------------------------------------------------------------------------
// Gate kernel: g_Gate[row][h] = sigmoid(X[row] . Wq[:, 1024+h] + bq[1024+h]).
// One warp per row; 16 heads via float4 loads. grid = MROWS/4, block = 128.
// ---------------------------------------------------------------------------
__global__ __launch_bounds__(128)
void gate_proj(const float* __restrict__ X, const float* __restrict__ Wq,
               const float* __restrict__ bq)
{
    const int warp = threadIdx.x >> 5;
    const int lane = threadIdx.x & 31;
    const int row  = blockIdx.x * 4 + warp;

    float acc[16] = {};
    for (int e = lane; e < EMB; e += 32) {
        const float xv = X[(size_t)row * EMB + e];
        const float* wrow = &Wq[(size_t)e * NQG + NH * HD];
        const float4 w0 = *(const float4*)&wrow[0];
        const float4 w1 = *(const float4*)&wrow[4];
        const float4 w2 = *(const float4*)&wrow[8];
        const float4 w3 = *(const float4*)&wrow[12];
        acc[0]  = fmaf(xv, w0.x, acc[0]);  acc[1]  = fmaf(xv, w0.y, acc[1]);
        acc[2]  = fmaf(xv, w0.z, acc[2]);  acc[3]  = fmaf(xv, w0.w, acc[3]);
        acc[4]  = fmaf(xv, w1.x, acc[4]);  acc[5]  = fmaf(xv, w1.y, acc[5]);
        acc[6]  = fmaf(xv, w1.z, acc[6]);  acc[7]  = fmaf(xv, w1.w, acc[7]);
        acc[8]  = fmaf(xv, w2.x, acc[8]);  acc[9]  = fmaf(xv, w2.y, acc[9]);
        acc[10] = fmaf(xv, w2.z, acc[10]); acc[11] = fmaf(xv, w2.w, acc[11]);
        acc[12] = fmaf(xv, w3.x, acc[12]); acc[13] = fmaf(xv, w3.y, acc[13]);
        acc[14] = fmaf(xv, w3.z, acc[14]); acc[15] = fmaf(xv, w3.w, acc[15]);
    }
#pragma unroll
    for (int h = 0; h < 16; ++h) {
#pragma unroll
        for (int off = 16; off >= 1; off >>= 1)
            acc[h] += __shfl_xor_sync(0xffffffffu, acc[h], off);
    }
    if (lane < 16) {
        const float logit = acc[lane] + bq[NH * HD + lane];
        g_Gate[(size_t)row * NH + lane] = 1.f / (1.f + __expf(-logit));
    }
}

// ---------------------------------------------------------------------------
// Flash attention + sigmoid gate. Static smem 44 KB. grid = (32, 32), 128 thr.
// Register-prefetch of next K/V tile hides global-load latency under compute.
// ---------------------------------------------------------------------------
#define QS_STRIDE 68
#define KS_STRIDE 36
#define PS_STRIDE 68
#define VS_STRIDE 68

__global__ __launch_bounds__(128, 4)
void flash_gated(const float* __restrict__ mask)
{
    __shared__ float Qs[64 * QS_STRIDE];  // [d][r], scale pre-applied
    __shared__ float Ks[64 * KS_STRIDE];  // [d][c]
    __shared__ float Ps[32 * PS_STRIDE];  // [t][r]
    __shared__ float Vs[32 * VS_STRIDE];  // [t][d]

    const int bh = blockIdx.y;
    const int b  = bh >> 4;
    const int h  = bh & 15;
    const int s0 = blockIdx.x * 64;

    const int tid = threadIdx.x;
    const int tx = tid & 7;
    const int ty = tid >> 3;
    const int r4 = ty * 4;
    const int c4 = tx * 4;
    const int d8 = tx * 8;

    const float scale = 0.125f;

    // load-mapping for K/V tiles (4 rows of 128-thread float4 loads)
    const int lc = tid >> 4;           // 0..7  (+8,+16,+24 over its)
    const int ld = (tid & 15) << 2;    // 0..60

    // ---- load Q tile (scaled) into Qs[d][r] ----
#pragma unroll
    for (int it = 0; it < 8; ++it) {
        int idx = tid + it * 128;
        int r  = idx >> 4;
        int dg = (idx & 15) << 2;
        float4 q = *(const float4*)&g_Q[(size_t)(b * SEQ + s0 + r) * EMB + h * HD + dg];
        Qs[(dg + 0) * QS_STRIDE + r] = q.x * scale;
        Qs[(dg + 1) * QS_STRIDE + r] = q.y * scale;
        Qs[(dg + 2) * QS_STRIDE + r] = q.z * scale;
        Qs[(dg + 3) * QS_STRIDE + r] = q.w * scale;
    }

    float o[4][8] = {};
    float m[4], l[4];
#pragma unroll
    for (int i = 0; i < 4; ++i) { m[i] = -INFINITY; l[i] = 0.f; }

    // prologue: prefetch tile 0
    float4 pk[4], pv[4];
#pragma unroll
    for (int it = 0; it < 4; ++it) {
        const int c = lc + it * 8;
        pk[it] = *(const float4*)&g_K[(size_t)(b * SEQ + c) * EMB + h * HD + ld];
        pv[it] = *(const float4*)&g_V[(size_t)(b * SEQ + c) * EMB + h * HD + ld];
    }

    for (int jt = 0; jt < SEQ / 32; ++jt) {
        const int t0 = jt * 32;
        __syncthreads();   // prev iter's Ps/Vs/Ks reads done; Qs ready first time

        // ---- store prefetched K/V tile ----
#pragma unroll
        for (int it = 0; it < 4; ++it) {
            const int c = lc + it * 8;
            Ks[(ld + 0) * KS_STRIDE + c] = pk[it].x;
            Ks[(ld + 1) * KS_STRIDE + c] = pk[it].y;
            Ks[(ld + 2) * KS_STRIDE + c] = pk[it].z;
            Ks[(ld + 3) * KS_STRIDE + c] = pk[it].w;
            *(float4*)&Vs[c * VS_STRIDE + ld] = pv[it];
        }
        __syncthreads();

        // ---- prefetch next tile (consumed after next top sync) ----
        if (jt + 1 < SEQ / 32) {
            const int tn = t0 + 32;
#pragma unroll
            for (int it = 0; it < 4; ++it) {
                const int c = tn + lc + it * 8;
                pk[it] = *(const float4*)&g_K[(size_t)(b * SEQ + c) * EMB + h * HD + ld];
                pv[it] = *(const float4*)&g_V[(size_t)(b * SEQ + c) * EMB + h * HD + ld];
            }
        }

        // ---- scores S = Q^T K ----
        float acc[4][4] = {};
#pragma unroll 8
        for (int d = 0; d < 64; ++d) {
            const float4 ra = *(const float4*)&Qs[d * QS_STRIDE + r4];
            const float4 rb = *(const float4*)&Ks[d * KS_STRIDE + c4];
            const float a0 = ra.x, a1 = ra.y, a2 = ra.z, a3 = ra.w;
            acc[0][0] = fmaf(a0, rb.x, acc[0][0]); acc[0][1] = fmaf(a0, rb.y, acc[0][1]);
            acc[0][2] = fmaf(a0, rb.z, acc[0][2]); acc[0][3] = fmaf(a0, rb.w, acc[0][3]);
            acc[1][0] = fmaf(a1, rb.x, acc[1][0]); acc[1][1] = fmaf(a1, rb.y, acc[1][1]);
            acc[1][2] = fmaf(a1, rb.z, acc[1][2]); acc[1][3] = fmaf(a1, rb.w, acc[1][3]);
            acc[2][0] = fmaf(a2, rb.x, acc[2][0]); acc[2][1] = fmaf(a2, rb.y, acc[2][1]);
            acc[2][2] = fmaf(a2, rb.z, acc[2][2]); acc[2][3] = fmaf(a2, rb.w, acc[2][3]);
            acc[3][0] = fmaf(a3, rb.x, acc[3][0]); acc[3][1] = fmaf(a3, rb.y, acc[3][1]);
            acc[3][2] = fmaf(a3, rb.z, acc[3][2]); acc[3][3] = fmaf(a3, rb.w, acc[3][3]);
        }

        // ---- add mask ----
#pragma unroll
        for (int i = 0; i < 4; ++i) {
            const float4 mk = *(const float4*)&mask[(size_t)(b * SEQ + s0 + r4 + i) * SEQ + t0 + c4];
            acc[i][0] += mk.x; acc[i][1] += mk.y; acc[i][2] += mk.z; acc[i][3] += mk.w;
        }

        // ---- online softmax (8 lanes share a row) ----
        float fac[4];
#pragma unroll
        for (int i = 0; i < 4; ++i) {
            float lm = fmaxf(fmaxf(acc[i][0], acc[i][1]), fmaxf(acc[i][2], acc[i][3]));
#pragma unroll
            for (int off = 4; off >= 1; off >>= 1)
                lm = fmaxf(lm, __shfl_xor_sync(0xffffffffu, lm, off, 8));
            const float mn = fmaxf(m[i], lm);
            fac[i] = __expf(m[i] - mn);
            float rs = 0.f;
#pragma unroll
            for (int j = 0; j < 4; ++j) {
                acc[i][j] = __expf(acc[i][j] - mn);
                rs += acc[i][j];
            }
#pragma unroll
            for (int off = 4; off >= 1; off >>= 1)
                rs += __shfl_xor_sync(0xffffffffu, rs, off, 8);
            l[i] = l[i] * fac[i] + rs;
            m[i] = mn;
        }

        // ---- write P (transposed [t][r]) ----
#pragma unroll
        for (int j = 0; j < 4; ++j)
#pragma unroll
            for (int i = 0; i < 4; ++i)
                Ps[(c4 + j) * PS_STRIDE + (r4 + i)] = acc[i][j];

        __syncthreads();

        // ---- O = O*fac + P @ V ----
#pragma unroll
        for (int i = 0; i < 4; ++i)
#pragma unroll
            for (int j = 0; j < 8; ++j)
                o[i][j] *= fac[i];

#pragma unroll 4
        for (int t = 0; t < 32; ++t) {
            const float4 rp = *(const float4*)&Ps[t * PS_STRIDE + r4];
            const float4 va = *(const float4*)&Vs[t * VS_STRIDE + d8];
            const float4 vb = *(const float4*)&Vs[t * VS_STRIDE + d8 + 4];
            const float p0 = rp.x, p1 = rp.y, p2 = rp.z, p3 = rp.w;
            o[0][0] = fmaf(p0, va.x, o[0][0]); o[0][1] = fmaf(p0, va.y, o[0][1]);
            o[0][2] = fmaf(p0, va.z, o[0][2]); o[0][3] = fmaf(p0, va.w, o[0][3]);
            o[0][4] = fmaf(p0, vb.x, o[0][4]); o[0][5] = fmaf(p0, vb.y, o[0][5]);
            o[0][6] = fmaf(p0, vb.z, o[0][6]); o[0][7] = fmaf(p0, vb.w, o[0][7]);
            o[1][0] = fmaf(p1, va.x, o[1][0]); o[1][1] = fmaf(p1, va.y, o[1][1]);
            o[1][2] = fmaf(p1, va.z, o[1][2]); o[1][3] = fmaf(p1, va.w, o[1][3]);
            o[1][4] = fmaf(p1, vb.x, o[1][4]); o[1][5] = fmaf(p1, vb.y, o[1][5]);
            o[1][6] = fmaf(p1, vb.z, o[1][6]); o[1][7] = fmaf(p1, vb.w, o[1][7]);
            o[2][0] = fmaf(p2, va.x, o[2][0]); o[2][1] = fmaf(p2, va.y, o[2][1]);
            o[2][2] = fmaf(p2, va.z, o[2][2]); o[2][3] = fmaf(p2, va.w, o[2][3]);
            o[2][4] = fmaf(p2, vb.x, o[2][4]); o[2][5] = fmaf(p2, vb.y, o[2][5]);
            o[2][6] = fmaf(p2, vb.z, o[2][6]); o[2][7] = fmaf(p2, vb.w, o[2][7]);
            o[3][0] = fmaf(p3, va.x, o[3][0]); o[3][1] = fmaf(p3, va.y, o[3][1]);
            o[3][2] = fmaf(p3, va.z, o[3][2]); o[3][3] = fmaf(p3, va.w, o[3][3]);
            o[3][4] = fmaf(p3, vb.x, o[3][4]); o[3][5] = fmaf(p3, vb.y, o[3][5]);
            o[3][6] = fmaf(p3, vb.z, o[3][6]); o[3][7] = fmaf(p3, vb.w, o[3][7]);
        }
    }

    // ---- epilogue: 1/l, gate, store ----
#pragma unroll
    for (int i = 0; i < 4; ++i) {
        const int srow = b * SEQ + s0 + r4 + i;
        const float gate = g_Gate[(size_t)srow * NH + h];
        const float inv_l = gate / l[i];
        float4 oa, ob;
        oa.x = o[i][0] * inv_l; oa.y = o[i][1] * inv_l;
        oa.z = o[i][2] * inv_l; oa.w = o[i][3] * inv_l;
        ob.x = o[i][4] * inv_l; ob.y = o[i][5] * inv_l;
        ob.z = o[i][6] * inv_l; ob.w = o[i][7] * inv_l;
        *(float4*)&g_AO[(size_t)srow * EMB + h * HD + d8]     = oa;
        *(float4*)&g_AO[(size_t)srow * EMB + h * HD + d8 + 4] = ob;
    }
}

// ---------------------------------------------------------------------------
// kernel_launch: KERNEL LAUNCHES ONLY (graph-capture safe).
// ---------------------------------------------------------------------------
extern "C" void kernel_launch(void* const* d_in, const int* in_sizes, int n_in,
                              void* d_out, int out_size)
{
    const float* X    = (const float*)d_in[0];
    const float* mask = (const float*)d_in[1];
    const float* Wq   = (const float*)d_in[2];
    const float* bq   = (const float*)d_in[3];
    const float* Wk   = (const float*)d_in[4];
    const float* bk   = (const float*)d_in[5];
    const float* Wv   = (const float*)d_in[6];
    const float* bv   = (const float*)d_in[7];
    const float* Wo   = (const float*)d_in[8];
    const float* bo   = (const float*)d_in[9];
    float* out = (float*)d_out;

    // Fused Q/K/V projections (z selects weight/dest)
    sgemm128<0><<<dim3(EMB / 128, MROWS / 128, 3), 256>>>(
        X, Wq, bq, Wk, bk, Wv, bv, nullptr);
    // Gate = sigmoid(X @ Wq[:, 1024:1040] + bq[1024:1040])
    gate_proj<<<MROWS / 4, 128>>>(X, Wq, bq);

    // Flash attention with gate -> g_AO
    flash_gated<<<dim3(SEQ / 64, BSZ * NH), 128>>>(mask);

    // out = g_AO @ Wo + bo
    sgemm128<1><<<dim3(EMB / 128, MROWS / 128, 1), 256>>>(
        nullptr, Wo, bo, nullptr, nullptr, nullptr, nullptr, out);
}

// round 11
// speedup vs baseline: 1.1547x; 1.0071x over previous
#include <cuda_runtime.h>
#include <math.h>

#define BSZ 2
#define SEQ 2048
#define EMB 1024
#define NH  16
#define HD  64
#define MROWS (BSZ * SEQ)          /* 4096 */
#define NQG   (NH * HD + NH)       /* 1040: Wq/bq cols (Q 0..1023, gates 1024..1039) */

typedef unsigned long long u64;

// ---- packed f32x2 helpers (Blackwell PTX; ptxas won't auto-fuse these) ----
__device__ __forceinline__ u64 ffma2(u64 a, u64 b, u64 c) {
    u64 d; asm("fma.rn.f32x2 %0, %1, %2, %3;" : "=l"(d) : "l"(a), "l"(b), "l"(c));
    return d;
}
__device__ __forceinline__ u64 fmul2(u64 a, u64 b) {
    u64 d; asm("mul.rn.f32x2 %0, %1, %2;" : "=l"(d) : "l"(a), "l"(b));
    return d;
}
__device__ __forceinline__ u64 bcast2(float x) {
    u64 d; unsigned xu = __float_as_uint(x);
    asm("mov.b64 %0, {%1, %1};" : "=l"(d) : "r"(xu));
    return d;
}
__device__ __forceinline__ float2 unpack2(u64 p) {
    unsigned lo, hi; asm("mov.b64 {%0, %1}, %2;" : "=r"(lo), "=r"(hi) : "l"(p));
    return make_float2(__uint_as_float(lo), __uint_as_float(hi));
}

// Scratch (static device globals — no allocation allowed anywhere)
__device__ float g_Q   [MROWS * EMB];
__device__ float g_Gate[MROWS * NH];
__device__ float g_K   [MROWS * EMB];
__device__ float g_V   [MROWS * EMB];
__device__ float g_AO  [MROWS * EMB];

// ---------------------------------------------------------------------------
// SGEMM 128x128x16, 256 threads, 8x8 split micro-tile, FFMA2 inner loop,
// register-prefetch double buffering. M=4096, N=1024, K=1024 fixed.
// MODE 0: fused QKV (blockIdx.z selects), MODE 1: out = g_AO @ Wo + bo
// ---------------------------------------------------------------------------
template<int MODE>
__global__ __launch_bounds__(256, 2)
void sgemm128(const float* __restrict__ X,
              const float* __restrict__ W0, const float* __restrict__ b0,
              const float* __restrict__ W1, const float* __restrict__ b1,
              const float* __restrict__ W2, const float* __restrict__ b2,
              float* __restrict__ outp)
{
    const float* A; const float* B; const float* bias; float* C; int ldb;
    if (MODE == 0) {
        A = X;
        const int z = blockIdx.z;
        if (z == 0)      { B = W0; bias = b0; C = g_Q; ldb = NQG; }
        else if (z == 1) { B = W1; bias = b1; C = g_K; ldb = EMB; }
        else             { B = W2; bias = b2; C = g_V; ldb = EMB; }
    } else {
        A = g_AO; B = W0; bias = b0; C = outp; ldb = EMB;
    }

    __shared__ float As[16][132];   // A^T tile: [k][m]
    __shared__ float Bs[16][132];   // B tile:   [k][n]

    const int tid = threadIdx.x;
    const int tx = tid & 15;
    const int ty = tid >> 4;
    const int row0 = blockIdx.y * 128;
    const int col0 = blockIdx.x * 128;

    const int arow = tid >> 2;
    const int akc  = (tid & 3) << 2;
    const int brow = tid >> 5;
    const int bcol = (tid & 31) << 2;

    float4 pa0, pa1, pb0, pb1;

    pa0 = *(const float4*)&A[(size_t)(row0 + arow) * EMB + akc];
    pa1 = *(const float4*)&A[(size_t)(row0 + arow + 64) * EMB + akc];
    pb0 = *(const float4*)&B[(size_t)(brow) * ldb + col0 + bcol];
    pb1 = *(const float4*)&B[(size_t)(brow + 8) * ldb + col0 + bcol];

    u64 acc2[8][4] = {};   // 8 rows x 4 col-pairs

    for (int kb = 0; kb < EMB; kb += 16) {
        __syncthreads();
        As[akc + 0][arow] = pa0.x;  As[akc + 1][arow] = pa0.y;
        As[akc + 2][arow] = pa0.z;  As[akc + 3][arow] = pa0.w;
        As[akc + 0][arow + 64] = pa1.x;  As[akc + 1][arow + 64] = pa1.y;
        As[akc + 2][arow + 64] = pa1.z;  As[akc + 3][arow + 64] = pa1.w;
        *(float4*)&Bs[brow][bcol]     = pb0;
        *(float4*)&Bs[brow + 8][bcol] = pb1;
        __syncthreads();

        if (kb + 16 < EMB) {
            pa0 = *(const float4*)&A[(size_t)(row0 + arow) * EMB + kb + 16 + akc];
            pa1 = *(const float4*)&A[(size_t)(row0 + arow + 64) * EMB + kb + 16 + akc];
            pb0 = *(const float4*)&B[(size_t)(kb + 16 + brow) * ldb + col0 + bcol];
            pb1 = *(const float4*)&B[(size_t)(kb + 16 + brow + 8) * ldb + col0 + bcol];
        }

#pragma unroll
        for (int k = 0; k < 16; ++k) {
            const float4 a0 = *(const float4*)&As[k][ty * 4];
            const float4 a1 = *(const float4*)&As[k][64 + ty * 4];
            const ulonglong2 bq0 = *(const ulonglong2*)&Bs[k][tx * 4];
            const ulonglong2 bq1 = *(const ulonglong2*)&Bs[k][64 + tx * 4];
            u64 rb[4]; rb[0] = bq0.x; rb[1] = bq0.y; rb[2] = bq1.x; rb[3] = bq1.y;
            u64 ra[8];
            ra[0] = bcast2(a0.x); ra[1] = bcast2(a0.y);
            ra[2] = bcast2(a0.z); ra[3] = bcast2(a0.w);
            ra[4] = bcast2(a1.x); ra[5] = bcast2(a1.y);
            ra[6] = bcast2(a1.z); ra[7] = bcast2(a1.w);
#pragma unroll
            for (int i = 0; i < 8; ++i)
#pragma unroll
                for (int j = 0; j < 4; ++j)
                    acc2[i][j] = ffma2(ra[i], rb[j], acc2[i][j]);
        }
    }

#pragma unroll
    for (int ih = 0; ih < 2; ++ih) {
#pragma unroll
        for (int i = 0; i < 4; ++i) {
            const int row = row0 + ih * 64 + ty * 4 + i;
#pragma unroll
            for (int jh = 0; jh < 2; ++jh) {
                const int col = col0 + jh * 64 + tx * 4;
                const float2 p0 = unpack2(acc2[ih * 4 + i][jh * 2 + 0]);
                const float2 p1 = unpack2(acc2[ih * 4 + i][jh * 2 + 1]);
                float4 o;
                o.x = p0.x + bias[col + 0];
                o.y = p0.y + bias[col + 1];
                o.z = p1.x + bias[col + 2];
                o.w = p1.y + bias[col + 3];
                *(float4*)&C[(size_t)row * EMB + col] = o;
            }
        }
    }
}

// ---------------------------------------------------------------------------
// Gate kernel: g_Gate[row][h] = sigmoid(X[row] . Wq[:, 1024+h] + bq[1024+h]).
// ---------------------------------------------------------------------------
__global__ __launch_bounds__(128)
void gate_proj(const float* __restrict__ X, const float* __restrict__ Wq,
               const float* __restrict__ bq)
{
    const int warp = threadIdx.x >> 5;
    const int lane = threadIdx.x & 31;
    const int row  = blockIdx.x * 4 + warp;

    float acc[16] = {};
    for (int e = lane; e < EMB; e += 32) {
        const float xv = X[(size_t)row * EMB + e];
        const float* wrow = &Wq[(size_t)e * NQG + NH * HD];
        const float4 w0 = *(const float4*)&wrow[0];
        const float4 w1 = *(const float4*)&wrow[4];
        const float4 w2 = *(const float4*)&wrow[8];
        const float4 w3 = *(const float4*)&wrow[12];
        acc[0]  = fmaf(xv, w0.x, acc[0]);  acc[1]  = fmaf(xv, w0.y, acc[1]);
        acc[2]  = fmaf(xv, w0.z, acc[2]);  acc[3]  = fmaf(xv, w0.w, acc[3]);
        acc[4]  = fmaf(xv, w1.x, acc[4]);  acc[5]  = fmaf(xv, w1.y, acc[5]);
        acc[6]  = fmaf(xv, w1.z, acc[6]);  acc[7]  = fmaf(xv, w1.w, acc[7]);
        acc[8]  = fmaf(xv, w2.x, acc[8]);  acc[9]  = fmaf(xv, w2.y, acc[9]);
        acc[10] = fmaf(xv, w2.z, acc[10]); acc[11] = fmaf(xv, w2.w, acc[11]);
        acc[12] = fmaf(xv, w3.x, acc[12]); acc[13] = fmaf(xv, w3.y, acc[13]);
        acc[14] = fmaf(xv, w3.z, acc[14]); acc[15] = fmaf(xv, w3.w, acc[15]);
    }
#pragma unroll
    for (int h = 0; h < 16; ++h) {
#pragma unroll
        for (int off = 16; off >= 1; off >>= 1)
            acc[h] += __shfl_xor_sync(0xffffffffu, acc[h], off);
    }
    if (lane < 16) {
        const float logit = acc[lane] + bq[NH * HD + lane];
        g_Gate[(size_t)row * NH + lane] = 1.f / (1.f + __expf(-logit));
    }
}

// ---------------------------------------------------------------------------
// Flash attention + sigmoid gate. Static smem 44 KB, 128 threads, FFMA2
// inner loops, K/V register prefetch (1 tile ahead), mask loads hoisted
// before the score loop so DRAM latency is covered by ~900 instrs of FMA.
// ---------------------------------------------------------------------------
#define QS_STRIDE 68
#define KS_STRIDE 36
#define PS_STRIDE 68
#define VS_STRIDE 68

__global__ __launch_bounds__(128, 4)
void flash_gated(const float* __restrict__ mask)
{
    __shared__ float Qs[64 * QS_STRIDE];  // [d][r], scale pre-applied
    __shared__ float Ks[64 * KS_STRIDE];  // [d][c]
    __shared__ float Ps[32 * PS_STRIDE];  // [t][r]
    __shared__ float Vs[32 * VS_STRIDE];  // [t][d]

    const int bh = blockIdx.y;
    const int b  = bh >> 4;
    const int h  = bh & 15;
    const int s0 = blockIdx.x * 64;

    const int tid = threadIdx.x;
    const int tx = tid & 7;
    const int ty = tid >> 3;
    const int r4 = ty * 4;
    const int c4 = tx * 4;
    const int d8 = tx * 8;

    const float scale = 0.125f;

    const int lc = tid >> 4;           // 0..7  (+8,+16,+24 over its)
    const int ld = (tid & 15) << 2;    // 0..60

    // ---- load Q tile (scaled) into Qs[d][r] ----
#pragma unroll
    for (int it = 0; it < 8; ++it) {
        int idx = tid + it * 128;
        int r  = idx >> 4;
        int dg = (idx & 15) << 2;
        float4 q = *(const float4*)&g_Q[(size_t)(b * SEQ + s0 + r) * EMB + h * HD + dg];
        Qs[(dg + 0) * QS_STRIDE + r] = q.x * scale;
        Qs[(dg + 1) * QS_STRIDE + r] = q.y * scale;
        Qs[(dg + 2) * QS_STRIDE + r] = q.z * scale;
        Qs[(dg + 3) * QS_STRIDE + r] = q.w * scale;
    }

    u64 op[4][4] = {};                 // 4 rows x 4 d-pairs (d8..d8+7)
    float m[4], l[4];
#pragma unroll
    for (int i = 0; i < 4; ++i) { m[i] = -INFINITY; l[i] = 0.f; }

    // prologue: prefetch K/V tile 0
    float4 pk[4], pv[4];
#pragma unroll
    for (int it = 0; it < 4; ++it) {
        const int c = lc + it * 8;
        pk[it] = *(const float4*)&g_K[(size_t)(b * SEQ + c) * EMB + h * HD + ld];
        pv[it] = *(const float4*)&g_V[(size_t)(b * SEQ + c) * EMB + h * HD + ld];
    }

    for (int jt = 0; jt < SEQ / 32; ++jt) {
        const int t0 = jt * 32;
        __syncthreads();

        // ---- store prefetched K/V tile ----
#pragma unroll
        for (int it = 0; it < 4; ++it) {
            const int c = lc + it * 8;
            Ks[(ld + 0) * KS_STRIDE + c] = pk[it].x;
            Ks[(ld + 1) * KS_STRIDE + c] = pk[it].y;
            Ks[(ld + 2) * KS_STRIDE + c] = pk[it].z;
            Ks[(ld + 3) * KS_STRIDE + c] = pk[it].w;
            *(float4*)&Vs[c * VS_STRIDE + ld] = pv[it];
        }
        __syncthreads();

        // ---- prefetch next K/V tile ----
        if (jt + 1 < SEQ / 32) {
            const int tn = t0 + 32;
#pragma unroll
            for (int it = 0; it < 4; ++it) {
                const int c = tn + lc + it * 8;
                pk[it] = *(const float4*)&g_K[(size_t)(b * SEQ + c) * EMB + h * HD + ld];
                pv[it] = *(const float4*)&g_V[(size_t)(b * SEQ + c) * EMB + h * HD + ld];
            }
        }

        // ---- mask loads hoisted: latency covered by the score loop ----
        float4 mk[4];
#pragma unroll
        for (int i = 0; i < 4; ++i)
            mk[i] = *(const float4*)&mask[(size_t)(b * SEQ + s0 + r4 + i) * SEQ + t0 + c4];

        // ---- scores S = Q^T K (FFMA2: row-pairs from Qs, col-broadcasts) ----
        u64 accp[2][4] = {};
#pragma unroll 8
        for (int d = 0; d < 64; ++d) {
            const ulonglong2 qa = *(const ulonglong2*)&Qs[d * QS_STRIDE + r4];
            const float4 rb = *(const float4*)&Ks[d * KS_STRIDE + c4];
            const u64 cb0 = bcast2(rb.x), cb1 = bcast2(rb.y);
            const u64 cb2 = bcast2(rb.z), cb3 = bcast2(rb.w);
            accp[0][0] = ffma2(qa.x, cb0, accp[0][0]);
            accp[0][1] = ffma2(qa.x, cb1, accp[0][1]);
            accp[0][2] = ffma2(qa.x, cb2, accp[0][2]);
            accp[0][3] = ffma2(qa.x, cb3, accp[0][3]);
            accp[1][0] = ffma2(qa.y, cb0, accp[1][0]);
            accp[1][1] = ffma2(qa.y, cb1, accp[1][1]);
            accp[1][2] = ffma2(qa.y, cb2, accp[1][2]);
            accp[1][3] = ffma2(qa.y, cb3, accp[1][3]);
        }

        // ---- unpack + add mask ----
        float acc[4][4];
#pragma unroll
        for (int j = 0; j < 4; ++j) {
            const float2 t01 = unpack2(accp[0][j]);
            const float2 t23 = unpack2(accp[1][j]);
            acc[0][j] = t01.x; acc[1][j] = t01.y;
            acc[2][j] = t23.x; acc[3][j] = t23.y;
        }
#pragma unroll
        for (int i = 0; i < 4; ++i) {
            acc[i][0] += mk[i].x; acc[i][1] += mk[i].y;
            acc[i][2] += mk[i].z; acc[i][3] += mk[i].w;
        }

        // ---- online softmax (8 lanes share a row) ----
        float fac[4];
#pragma unroll
        for (int i = 0; i < 4; ++i) {
            float lm = fmaxf(fmaxf(acc[i][0], acc[i][1]), fmaxf(acc[i][2], acc[i][3]));
#pragma unroll
            for (int off = 4; off >= 1; off >>= 1)
                lm = fmaxf(lm, __shfl_xor_sync(0xffffffffu, lm, off, 8));
            const float mn = fmaxf(m[i], lm);
            fac[i] = __expf(m[i] - mn);
            float rs = 0.f;
#pragma unroll
            for (int j = 0; j < 4; ++j) {
                acc[i][j] = __expf(acc[i][j] - mn);
                rs += acc[i][j];
            }
#pragma unroll
            for (int off = 4; off >= 1; off >>= 1)
                rs += __shfl_xor_sync(0xffffffffu, rs, off, 8);
            l[i] = l[i] * fac[i] + rs;
            m[i] = mn;
        }

        // ---- write P (transposed [t][r]) ----
#pragma unroll
        for (int j = 0; j < 4; ++j)
#pragma unroll
            for (int i = 0; i < 4; ++i)
                Ps[(c4 + j) * PS_STRIDE + (r4 + i)] = acc[i][j];

        __syncthreads();

        // ---- O = O*fac + P @ V  (FFMA2: d-pairs from Vs, row-broadcasts) ----
#pragma unroll
        for (int i = 0; i < 4; ++i) {
            const u64 f2 = bcast2(fac[i]);
#pragma unroll
            for (int j = 0; j < 4; ++j)
                op[i][j] = fmul2(op[i][j], f2);
        }

#pragma unroll 4
        for (int t = 0; t < 32; ++t) {
            const float4 rp = *(const float4*)&Ps[t * PS_STRIDE + r4];
            const ulonglong2 va = *(const ulonglong2*)&Vs[t * VS_STRIDE + d8];
            const ulonglong2 vb = *(const ulonglong2*)&Vs[t * VS_STRIDE + d8 + 4];
            const u64 pb0 = bcast2(rp.x), pb1 = bcast2(rp.y);
            const u64 pb2 = bcast2(rp.z), pb3 = bcast2(rp.w);
            op[0][0] = ffma2(pb0, va.x, op[0][0]);
            op[0][1] = ffma2(pb0, va.y, op[0][1]);
            op[0][2] = ffma2(pb0, vb.x, op[0][2]);
            op[0][3] = ffma2(pb0, vb.y, op[0][3]);
            op[1][0] = ffma2(pb1, va.x, op[1][0]);
            op[1][1] = ffma2(pb1, va.y, op[1][1]);
            op[1][2] = ffma2(pb1, vb.x, op[1][2]);
            op[1][3] = ffma2(pb1, vb.y, op[1][3]);
            op[2][0] = ffma2(pb2, va.x, op[2][0]);
            op[2][1] = ffma2(pb2, va.y, op[2][1]);
            op[2][2] = ffma2(pb2, vb.x, op[2][2]);
            op[2][3] = ffma2(pb2, vb.y, op[2][3]);
            op[3][0] = ffma2(pb3, va.x, op[3][0]);
            op[3][1] = ffma2(pb3, va.y, op[3][1]);
            op[3][2] = ffma2(pb3, vb.x, op[3][2]);
            op[3][3] = ffma2(pb3, vb.y, op[3][3]);
        }
    }

    // ---- epilogue: 1/l, gate, store ----
#pragma unroll
    for (int i = 0; i < 4; ++i) {
        const int srow = b * SEQ + s0 + r4 + i;
        const float gate = g_Gate[(size_t)srow * NH + h];
        const float inv_l = gate / l[i];
        const float2 q0 = unpack2(op[i][0]);
        const float2 q1 = unpack2(op[i][1]);
        const float2 q2 = unpack2(op[i][2]);
        const float2 q3 = unpack2(op[i][3]);
        float4 oa, ob;
        oa.x = q0.x * inv_l; oa.y = q0.y * inv_l;
        oa.z = q1.x * inv_l; oa.w = q1.y * inv_l;
        ob.x = q2.x * inv_l; ob.y = q2.y * inv_l;
        ob.z = q3.x * inv_l; ob.w = q3.y * inv_l;
        *(float4*)&g_AO[(size_t)srow * EMB + h * HD + d8]     = oa;
        *(float4*)&g_AO[(size_t)srow * EMB + h * HD + d8 + 4] = ob;
    }
}

// ---------------------------------------------------------------------------
// kernel_launch: KERNEL LAUNCHES ONLY (graph-capture safe).
// ---------------------------------------------------------------------------
extern "C" void kernel_launch(void* const* d_in, const int* in_sizes, int n_in,
                              void* d_out, int out_size)
{
    const float* X    = (const float*)d_in[0];
    const float* mask = (const float*)d_in[1];
    const float* Wq   = (const float*)d_in[2];
    const float* bq   = (const float*)d_in[3];
    const float* Wk   = (const float*)d_in[4];
    const float* bk   = (const float*)d_in[5];
    const float* Wv   = (const float*)d_in[6];
    const float* bv   = (const float*)d_in[7];
    const float* Wo   = (const float*)d_in[8];
    const float* bo   = (const float*)d_in[9];
    float* out = (float*)d_out;

    sgemm128<0><<<dim3(EMB / 128, MROWS / 128, 3), 256>>>(
        X, Wq, bq, Wk, bk, Wv, bv, nullptr);
    gate_proj<<<MROWS / 4, 128>>>(X, Wq, bq);

    flash_gated<<<dim3(SEQ / 64, BSZ * NH), 128>>>(mask);

    sgemm128<1><<<dim3(EMB / 128, MROWS / 128, 1), 256>>>(
        nullptr, Wo, bo, nullptr, nullptr, nullptr, nullptr, out);
}

// round 14
// speedup vs baseline: 1.1741x; 1.0168x over previous
#include <cuda_runtime.h>
#include <math.h>

#define BSZ 2
#define SEQ 2048
#define EMB 1024
#define NH  16
#define HD  64
#define MROWS (BSZ * SEQ)          /* 4096 */
#define NQG   (NH * HD + NH)       /* 1040: Wq/bq cols (Q 0..1023, gates 1024..1039) */

typedef unsigned long long u64;

// ---- packed f32x2 helpers (Blackwell PTX) ----
__device__ __forceinline__ u64 ffma2(u64 a, u64 b, u64 c) {
    u64 d; asm("fma.rn.f32x2 %0, %1, %2, %3;" : "=l"(d) : "l"(a), "l"(b), "l"(c));
    return d;
}
__device__ __forceinline__ u64 fmul2(u64 a, u64 b) {
    u64 d; asm("mul.rn.f32x2 %0, %1, %2;" : "=l"(d) : "l"(a), "l"(b));
    return d;
}
__device__ __forceinline__ u64 bcast2(float x) {
    u64 d; unsigned xu = __float_as_uint(x);
    asm("mov.b64 %0, {%1, %1};" : "=l"(d) : "r"(xu));
    return d;
}
__device__ __forceinline__ float2 unpack2(u64 p) {
    unsigned lo, hi; asm("mov.b64 {%0, %1}, %2;" : "=r"(lo), "=r"(hi) : "l"(p));
    return make_float2(__uint_as_float(lo), __uint_as_float(hi));
}

// Scratch (static device globals — no allocation allowed anywhere)
__device__ float g_Q   [MROWS * EMB];
__device__ float g_Gate[MROWS * NH];
__device__ float g_K   [MROWS * EMB];
__device__ float g_V   [MROWS * EMB];
__device__ float g_AO  [MROWS * EMB];

// ---------------------------------------------------------------------------
// SGEMM 128x128x16 (measured 174 us per 1024-col GEMM).
// MODE 0: fused QKV (blockIdx.z selects), MODE 1: out = g_AO @ Wo + bo
// ---------------------------------------------------------------------------
template<int MODE>
__global__ __launch_bounds__(256, 2)
void sgemm128(const float* __restrict__ X,
              const float* __restrict__ W0, const float* __restrict__ b0,
              const float* __restrict__ W1, const float* __restrict__ b1,
              const float* __restrict__ W2, const float* __restrict__ b2,
              float* __restrict__ outp)
{
    const float* A; const float* B; const float* bias; float* C; int ldb;
    if (MODE == 0) {
        A = X;
        const int z = blockIdx.z;
        if (z == 0)      { B = W0; bias = b0; C = g_Q; ldb = NQG; }
        else if (z == 1) { B = W1; bias = b1; C = g_K; ldb = EMB; }
        else             { B = W2; bias = b2; C = g_V; ldb = EMB; }
    } else {
        A = g_AO; B = W0; bias = b0; C = outp; ldb = EMB;
    }

    __shared__ float As[16][132];
    __shared__ float Bs[16][132];

    const int tid = threadIdx.x;
    const int tx = tid & 15;
    const int ty = tid >> 4;
    const int row0 = blockIdx.y * 128;
    const int col0 = blockIdx.x * 128;

    const int arow = tid >> 2;
    const int akc  = (tid & 3) << 2;
    const int brow = tid >> 5;
    const int bcol = (tid & 31) << 2;

    float4 pa0, pa1, pb0, pb1;

    pa0 = *(const float4*)&A[(size_t)(row0 + arow) * EMB + akc];
    pa1 = *(const float4*)&A[(size_t)(row0 + arow + 64) * EMB + akc];
    pb0 = *(const float4*)&B[(size_t)(brow) * ldb + col0 + bcol];
    pb1 = *(const float4*)&B[(size_t)(brow + 8) * ldb + col0 + bcol];

    u64 acc2[8][4] = {};

    for (int kb = 0; kb < EMB; kb += 16) {
        __syncthreads();
        As[akc + 0][arow] = pa0.x;  As[akc + 1][arow] = pa0.y;
        As[akc + 2][arow] = pa0.z;  As[akc + 3][arow] = pa0.w;
        As[akc + 0][arow + 64] = pa1.x;  As[akc + 1][arow + 64] = pa1.y;
        As[akc + 2][arow + 64] = pa1.z;  As[akc + 3][arow + 64] = pa1.w;
        *(float4*)&Bs[brow][bcol]     = pb0;
        *(float4*)&Bs[brow + 8][bcol] = pb1;
        __syncthreads();

        if (kb + 16 < EMB) {
            pa0 = *(const float4*)&A[(size_t)(row0 + arow) * EMB + kb + 16 + akc];
            pa1 = *(const float4*)&A[(size_t)(row0 + arow + 64) * EMB + kb + 16 + akc];
            pb0 = *(const float4*)&B[(size_t)(kb + 16 + brow) * ldb + col0 + bcol];
            pb1 = *(const float4*)&B[(size_t)(kb + 16 + brow + 8) * ldb + col0 + bcol];
        }

#pragma unroll
        for (int k = 0; k < 16; ++k) {
            const float4 a0 = *(const float4*)&As[k][ty * 4];
            const float4 a1 = *(const float4*)&As[k][64 + ty * 4];
            const ulonglong2 bq0 = *(const ulonglong2*)&Bs[k][tx * 4];
            const ulonglong2 bq1 = *(const ulonglong2*)&Bs[k][64 + tx * 4];
            u64 rb[4]; rb[0] = bq0.x; rb[1] = bq0.y; rb[2] = bq1.x; rb[3] = bq1.y;
            u64 ra[8];
            ra[0] = bcast2(a0.x); ra[1] = bcast2(a0.y);
            ra[2] = bcast2(a0.z); ra[3] = bcast2(a0.w);
            ra[4] = bcast2(a1.x); ra[5] = bcast2(a1.y);
            ra[6] = bcast2(a1.z); ra[7] = bcast2(a1.w);
#pragma unroll
            for (int i = 0; i < 8; ++i)
#pragma unroll
                for (int j = 0; j < 4; ++j)
                    acc2[i][j] = ffma2(ra[i], rb[j], acc2[i][j]);
        }
    }

#pragma unroll
    for (int ih = 0; ih < 2; ++ih) {
#pragma unroll
        for (int i = 0; i < 4; ++i) {
            const int row = row0 + ih * 64 + ty * 4 + i;
#pragma unroll
            for (int jh = 0; jh < 2; ++jh) {
                const int col = col0 + jh * 64 + tx * 4;
                const float2 p0 = unpack2(acc2[ih * 4 + i][jh * 2 + 0]);
                const float2 p1 = unpack2(acc2[ih * 4 + i][jh * 2 + 1]);
                float4 o;
                o.x = p0.x + bias[col + 0];
                o.y = p0.y + bias[col + 1];
                o.z = p1.x + bias[col + 2];
                o.w = p1.y + bias[col + 3];
                *(float4*)&C[(size_t)row * EMB + col] = o;
            }
        }
    }
}

// ---------------------------------------------------------------------------
// Gate kernel: g_Gate[row][h] = sigmoid(X[row] . Wq[:, 1024+h] + bq[1024+h]).
// ---------------------------------------------------------------------------
__global__ __launch_bounds__(128)
void gate_proj(const float* __restrict__ X, const float* __restrict__ Wq,
               const float* __restrict__ bq)
{
    const int warp = threadIdx.x >> 5;
    const int lane = threadIdx.x & 31;
    const int row  = blockIdx.x * 4 + warp;

    float acc[16] = {};
    for (int e = lane; e < EMB; e += 32) {
        const float xv = X[(size_t)row * EMB + e];
        const float* wrow = &Wq[(size_t)e * NQG + NH * HD];
        const float4 w0 = *(const float4*)&wrow[0];
        const float4 w1 = *(const float4*)&wrow[4];
        const float4 w2 = *(const float4*)&wrow[8];
        const float4 w3 = *(const float4*)&wrow[12];
        acc[0]  = fmaf(xv, w0.x, acc[0]);  acc[1]  = fmaf(xv, w0.y, acc[1]);
        acc[2]  = fmaf(xv, w0.z, acc[2]);  acc[3]  = fmaf(xv, w0.w, acc[3]);
        acc[4]  = fmaf(xv, w1.x, acc[4]);  acc[5]  = fmaf(xv, w1.y, acc[5]);
        acc[6]  = fmaf(xv, w1.z, acc[6]);  acc[7]  = fmaf(xv, w1.w, acc[7]);
        acc[8]  = fmaf(xv, w2.x, acc[8]);  acc[9]  = fmaf(xv, w2.y, acc[9]);
        acc[10] = fmaf(xv, w2.z, acc[10]); acc[11] = fmaf(xv, w2.w, acc[11]);
        acc[12] = fmaf(xv, w3.x, acc[12]); acc[13] = fmaf(xv, w3.y, acc[13]);
        acc[14] = fmaf(xv, w3.z, acc[14]); acc[15] = fmaf(xv, w3.w, acc[15]);
    }
#pragma unroll
    for (int h = 0; h < 16; ++h) {
#pragma unroll
        for (int off = 16; off >= 1; off >>= 1)
            acc[h] += __shfl_xor_sync(0xffffffffu, acc[h], off);
    }
    if (lane < 16) {
        const float logit = acc[lane] + bq[NH * HD + lane];
        g_Gate[(size_t)row * NH + lane] = 1.f / (1.f + __expf(-logit));
    }
}

// ---------------------------------------------------------------------------
// Flash attention + gate, v2: natural-layout smem with 16B-group XOR swizzle.
//   Qs [r][d] 64x64, Ks [c][d] 32x64, Vs [t][d] 32x64, Ps [r][t] 64x32 = 40KB
// Swizzle: float4-group g' = g ^ (row>>2); conflict-free in all hot loops.
// Scores are dot-products over d-pairs via FFMA2 (no broadcasts in score loop).
// grid = (32, 32), 128 threads, 3 syncs/iter, pk/pv prefetch issued at PV
// start so LDG latency hides under ~700 instrs and never overlaps score accs.
// ---------------------------------------------------------------------------
#define SWZ(row, g) ((g) ^ ((row) >> 2))              /* Qs/Ks/Vs: g 0..15 */
#define SWZP(row, g) ((g) ^ (((row) >> 2) & 7))       /* Ps: g 0..7 */

__global__ __launch_bounds__(128, 4)
void flash_gated(const float* __restrict__ mask)
{
    __shared__ float Qs[64 * 64];   // [r][d], scale pre-applied, swizzled
    __shared__ float Ks[32 * 64];   // [c][d], swizzled
    __shared__ float Vs[32 * 64];   // [t][d], swizzled
    __shared__ float Ps[64 * 32];   // [r][t], swizzled

    const int bh = blockIdx.y;
    const int b  = bh >> 4;
    const int h  = bh & 15;
    const int s0 = blockIdx.x * 64;

    const int tid = threadIdx.x;
    const int tx = tid & 7;    // score cols c4 = tx*4; PV d-cols d8 = tx*8
    const int ty = tid >> 3;   // score rows r4 = ty*4
    const int r4 = ty * 4;
    const int c4 = tx * 4;
    const int d8 = tx * 8;

    const float scale = 0.125f;

    // K/V tile load mapping: token c = lc + it*8 (it 0..3), float4-group lg
    const int lc = tid >> 4;           // 0..7
    const int lg = tid & 15;           // 0..15

    // ---- load Q tile (scaled) into Qs[r][d] swizzled ----
#pragma unroll
    for (int it = 0; it < 8; ++it) {
        const int r = (tid >> 4) + it * 8;       // 0..63
        float4 q = *(const float4*)&g_Q[(size_t)(b * SEQ + s0 + r) * EMB + h * HD + lg * 4];
        q.x *= scale; q.y *= scale; q.z *= scale; q.w *= scale;
        *(float4*)&Qs[r * 64 + SWZ(r, lg) * 4] = q;
    }

    u64 op[4][4] = {};                 // 4 rows x 4 d-pairs (d8..d8+7)
    float m[4], l[4];
#pragma unroll
    for (int i = 0; i < 4; ++i) { m[i] = -INFINITY; l[i] = 0.f; }

    // prologue: prefetch K/V tile 0
    float4 pk[4], pv[4];
#pragma unroll
    for (int it = 0; it < 4; ++it) {
        const int c = lc + it * 8;
        pk[it] = *(const float4*)&g_K[(size_t)(b * SEQ + c) * EMB + h * HD + lg * 4];
        pv[it] = *(const float4*)&g_V[(size_t)(b * SEQ + c) * EMB + h * HD + lg * 4];
    }

    for (int jt = 0; jt < SEQ / 32; ++jt) {
        const int t0 = jt * 32;
        __syncthreads();   // prev scores (Ks) + PV (Vs, Ps) reads done

        // ---- store prefetched K/V tiles (vector stores, swizzled) ----
#pragma unroll
        for (int it = 0; it < 4; ++it) {
            const int c = lc + it * 8;
            *(float4*)&Ks[c * 64 + SWZ(c, lg) * 4] = pk[it];
            *(float4*)&Vs[c * 64 + SWZ(c, lg) * 4] = pv[it];
        }
        __syncthreads();

        // ---- hoisted mask loads (covered by score loop) ----
        float4 mk[4];
#pragma unroll
        for (int i = 0; i < 4; ++i)
            mk[i] = *(const float4*)&mask[(size_t)(b * SEQ + s0 + r4 + i) * SEQ + t0 + c4];

        // ---- scores: dot-products over d-pairs, acc2[i][j] packs (even,odd) ----
        u64 acc2[4][4] = {};
#pragma unroll
        for (int dc = 0; dc < 16; ++dc) {          // d-chunk of 4 (one float4)
            ulonglong2 q[4];
#pragma unroll
            for (int i = 0; i < 4; ++i)
                q[i] = *(const ulonglong2*)&Qs[(r4 + i) * 64 + SWZ(r4 + i, dc) * 4];
#pragma unroll
            for (int j = 0; j < 4; ++j) {
                const ulonglong2 k = *(const ulonglong2*)&Ks[(c4 + j) * 64 + SWZ(c4 + j, dc) * 4];
#pragma unroll
                for (int i = 0; i < 4; ++i) {
                    acc2[i][j] = ffma2(q[i].x, k.x, acc2[i][j]);
                    acc2[i][j] = ffma2(q[i].y, k.y, acc2[i][j]);
                }
            }
        }

        // ---- horizontal add + mask ----
        float acc[4][4];
#pragma unroll
        for (int i = 0; i < 4; ++i) {
            float2 s0p = unpack2(acc2[i][0]);
            float2 s1p = unpack2(acc2[i][1]);
            float2 s2p = unpack2(acc2[i][2]);
            float2 s3p = unpack2(acc2[i][3]);
            acc[i][0] = s0p.x + s0p.y + mk[i].x;
            acc[i][1] = s1p.x + s1p.y + mk[i].y;
            acc[i][2] = s2p.x + s2p.y + mk[i].z;
            acc[i][3] = s3p.x + s3p.y + mk[i].w;
        }

        // ---- online softmax (8 lanes share a row) ----
        float fac[4];
#pragma unroll
        for (int i = 0; i < 4; ++i) {
            float lm = fmaxf(fmaxf(acc[i][0], acc[i][1]), fmaxf(acc[i][2], acc[i][3]));
#pragma unroll
            for (int off = 4; off >= 1; off >>= 1)
                lm = fmaxf(lm, __shfl_xor_sync(0xffffffffu, lm, off, 8));
            const float mn = fmaxf(m[i], lm);
            fac[i] = __expf(m[i] - mn);
            float rs = 0.f;
#pragma unroll
            for (int j = 0; j < 4; ++j) {
                acc[i][j] = __expf(acc[i][j] - mn);
                rs += acc[i][j];
            }
#pragma unroll
            for (int off = 4; off >= 1; off >>= 1)
                rs += __shfl_xor_sync(0xffffffffu, rs, off, 8);
            l[i] = l[i] * fac[i] + rs;
            m[i] = mn;
        }

        // ---- store P natural [r][t] (1 STS.128 per row, swizzled) ----
#pragma unroll
        for (int i = 0; i < 4; ++i) {
            float4 p; p.x = acc[i][0]; p.y = acc[i][1]; p.z = acc[i][2]; p.w = acc[i][3];
            *(float4*)&Ps[(r4 + i) * 32 + SWZP(r4 + i, tx) * 4] = p;
        }
        __syncthreads();

        // ---- prefetch next K/V tile (latency hidden under PV loop) ----
        if (jt + 1 < SEQ / 32) {
            const int tn = t0 + 32;
#pragma unroll
            for (int it = 0; it < 4; ++it) {
                const int c = tn + lc + it * 8;
                pk[it] = *(const float4*)&g_K[(size_t)(b * SEQ + c) * EMB + h * HD + lg * 4];
                pv[it] = *(const float4*)&g_V[(size_t)(b * SEQ + c) * EMB + h * HD + lg * 4];
            }
        }

        // ---- O = O*fac + P @ V ----
#pragma unroll
        for (int i = 0; i < 4; ++i) {
            const u64 f2 = bcast2(fac[i]);
#pragma unroll
            for (int j = 0; j < 4; ++j)
                op[i][j] = fmul2(op[i][j], f2);
        }

#pragma unroll
        for (int tc = 0; tc < 8; ++tc) {           // t-chunk of 4
            float4 rp[4];
#pragma unroll
            for (int i = 0; i < 4; ++i)
                rp[i] = *(const float4*)&Ps[(r4 + i) * 32 + SWZP(r4 + i, tc) * 4];
#pragma unroll
            for (int u = 0; u < 4; ++u) {
                const int t = tc * 4 + u;
                const u64 vA0 = *(const u64*)&Vs[t * 64 + SWZ(t, 2 * tx) * 4];
                const u64 vA1 = *(const u64*)&Vs[t * 64 + SWZ(t, 2 * tx) * 4 + 2];
                const u64 vB0 = *(const u64*)&Vs[t * 64 + SWZ(t, 2 * tx + 1) * 4];
                const u64 vB1 = *(const u64*)&Vs[t * 64 + SWZ(t, 2 * tx + 1) * 4 + 2];
                const float pu0 = (u == 0) ? rp[0].x : (u == 1) ? rp[0].y : (u == 2) ? rp[0].z : rp[0].w;
                const float pu1 = (u == 0) ? rp[1].x : (u == 1) ? rp[1].y : (u == 2) ? rp[1].z : rp[1].w;
                const float pu2 = (u == 0) ? rp[2].x : (u == 1) ? rp[2].y : (u == 2) ? rp[2].z : rp[2].w;
                const float pu3 = (u == 0) ? rp[3].x : (u == 1) ? rp[3].y : (u == 2) ? rp[3].z : rp[3].w;
                const u64 pb0 = bcast2(pu0), pb1 = bcast2(pu1);
                const u64 pb2 = bcast2(pu2), pb3 = bcast2(pu3);
                op[0][0] = ffma2(pb0, vA0, op[0][0]);
                op[0][1] = ffma2(pb0, vA1, op[0][1]);
                op[0][2] = ffma2(pb0, vB0, op[0][2]);
                op[0][3] = ffma2(pb0, vB1, op[0][3]);
                op[1][0] = ffma2(pb1, vA0, op[1][0]);
                op[1][1] = ffma2(pb1, vA1, op[1][1]);
                op[1][2] = ffma2(pb1, vB0, op[1][2]);
                op[1][3] = ffma2(pb1, vB1, op[1][3]);
                op[2][0] = ffma2(pb2, vA0, op[2][0]);
                op[2][1] = ffma2(pb2, vA1, op[2][1]);
                op[2][2] = ffma2(pb2, vB0, op[2][2]);
                op[2][3] = ffma2(pb2, vB1, op[2][3]);
                op[3][0] = ffma2(pb3, vA0, op[3][0]);
                op[3][1] = ffma2(pb3, vA1, op[3][1]);
                op[3][2] = ffma2(pb3, vB0, op[3][2]);
                op[3][3] = ffma2(pb3, vB1, op[3][3]);
            }
        }
    }

    // ---- epilogue: 1/l, gate, store ----
    // op[i][0..1] cover d8..d8+3 (logical group 2tx), op[i][2..3] d8+4..d8+7.
#pragma unroll
    for (int i = 0; i < 4; ++i) {
        const int srow = b * SEQ + s0 + r4 + i;
        const float gate = g_Gate[(size_t)srow * NH + h];
        const float inv_l = gate / l[i];
        const float2 q0 = unpack2(op[i][0]);
        const float2 q1 = unpack2(op[i][1]);
        const float2 q2 = unpack2(op[i][2]);
        const float2 q3 = unpack2(op[i][3]);
        float4 oa, ob;
        oa.x = q0.x * inv_l; oa.y = q0.y * inv_l;
        oa.z = q1.x * inv_l; oa.w = q1.y * inv_l;
        ob.x = q2.x * inv_l; ob.y = q2.y * inv_l;
        ob.z = q3.x * inv_l; ob.w = q3.y * inv_l;
        *(float4*)&g_AO[(size_t)srow * EMB + h * HD + d8]     = oa;
        *(float4*)&g_AO[(size_t)srow * EMB + h * HD + d8 + 4] = ob;
    }
}

// ---------------------------------------------------------------------------
// kernel_launch: KERNEL LAUNCHES ONLY (graph-capture safe).
// ---------------------------------------------------------------------------
extern "C" void kernel_launch(void* const* d_in, const int* in_sizes, int n_in,
                              void* d_out, int out_size)
{
    const float* X    = (const float*)d_in[0];
    const float* mask = (const float*)d_in[1];
    const float* Wq   = (const float*)d_in[2];
    const float* bq   = (const float*)d_in[3];
    const float* Wk   = (const float*)d_in[4];
    const float* bk   = (const float*)d_in[5];
    const float* Wv   = (const float*)d_in[6];
    const float* bv   = (const float*)d_in[7];
    const float* Wo   = (const float*)d_in[8];
    const float* bo   = (const float*)d_in[9];
    float* out = (float*)d_out;

    sgemm128<0><<<dim3(EMB / 128, MROWS / 128, 3), 256>>>(
        X, Wq, bq, Wk, bk, Wv, bv, nullptr);
    gate_proj<<<MROWS / 4, 128>>>(X, Wq, bq);

    flash_gated<<<dim3(SEQ / 64, BSZ * NH), 128>>>(mask);

    sgemm128<1><<<dim3(EMB / 128, MROWS / 128, 1), 256>>>(
        nullptr, Wo, bo, nullptr, nullptr, nullptr, nullptr, out);
}